// round 9
// baseline (speedup 1.0000x reference)
#include <cuda_runtime.h>
#include <cstdint>
#include <math.h>

// ---------------- problem constants ----------------
#define B_SZ 4
#define T_SZ 2048
#define D_SZ 1024
#define M_SZ (B_SZ * T_SZ)
#define MD   ((long)M_SZ * D_SZ)
#define DD   ((long)D_SZ * D_SZ)
#define ETA_C 0.1f
#define LCA_GEMM_ITERS 9   // iteration 1 fused into QKV epilogue

// ---------------- scratch (device globals; no allocation) ----------------
__device__ float g_u3[3 * M_SZ * D_SZ];      // u_q, u_k, v (fp32; z-indexed)
__device__ float g_vt[M_SZ * D_SZ];          // V^T per batch [B][D][T] (tf32-rounded)
__device__ float g_vs[2 * M_SZ * D_SZ];      // LCA v-state (fp32)
__device__ float g_ab[2][2 * M_SZ * D_SZ];   // LCA codes ping-pong x (q,k) (tf32-rounded)
__device__ float g_G2[2 * D_SZ * D_SZ];      // sym zero-diag Gq,Gk (tf32-rounded)
__device__ float g_S[(size_t)B_SZ * T_SZ * T_SZ];   // scores / probs
__device__ float g_o[M_SZ * D_SZ];           // attention out (tf32-rounded)
__device__ float g_xr[M_SZ * D_SZ];          // x rounded
__device__ float g_wqkvr[3 * D_SZ * D_SZ];   // W_qkv rounded
__device__ float g_woutr[D_SZ * D_SZ];       // W_out rounded

// ---------------- helpers ----------------
__device__ __forceinline__ uint32_t smem_u32(const void* p) {
    uint32_t a;
    asm("{ .reg .u64 t; cvta.to.shared.u64 t, %1; cvt.u32.u64 %0, t; }" : "=r"(a) : "l"(p));
    return a;
}
__device__ __forceinline__ void cp_async16(uint32_t dst, const void* src) {
    asm volatile("cp.async.cg.shared.global [%0], [%1], 16;" :: "r"(dst), "l"(src));
}
#define CP_COMMIT() asm volatile("cp.async.commit_group;" ::: "memory")
#define CP_WAIT2()  asm volatile("cp.async.wait_group 2;" ::: "memory")
#define CP_WAIT1()  asm volatile("cp.async.wait_group 1;" ::: "memory")
#define CP_WAIT0()  asm volatile("cp.async.wait_group 0;" ::: "memory")

__device__ __forceinline__ uint32_t f2tf32(float f) {
    uint32_t r;
    asm("cvt.rna.tf32.f32 %0, %1;" : "=r"(r) : "f"(f));
    return r;
}
__device__ __forceinline__ float rtf(float f) { return __uint_as_float(f2tf32(f)); }

__device__ __forceinline__ void mma_tf32(float* c, const uint32_t* a, const uint32_t* b) {
    asm volatile(
        "mma.sync.aligned.m16n8k8.row.col.f32.tf32.tf32.f32 "
        "{%0,%1,%2,%3}, {%4,%5,%6,%7}, {%8,%9}, {%0,%1,%2,%3};"
        : "+f"(c[0]), "+f"(c[1]), "+f"(c[2]), "+f"(c[3])
        : "r"(a[0]), "r"(a[1]), "r"(a[2]), "r"(a[3]), "r"(b[0]), "r"(b[1]));
}

// ---------------- GEMM (NT): C[m,n] = alpha * sum_k A[m,k]*B[n,k] ----------------
// 128x128 CTA tile, ONE 512-thread CTA per SM: 16 warps in a 4x4 grid of 32x32
// warp tiles (acc 32 regs/thread -> ptxas slack for fragment prefetch).
// 4-stage cp.async pipeline (3 chunks in flight), one __syncthreads per chunk.
// Inputs pre-rounded tf32; k-permuted layout for uint2 fragment loads:
//   mma-k (o,lc)->col 8o+2lc, (o,lc+4)->col 8o+2lc+1 (A and B consistent).
#define MODE_QKV   0   // plain GEMM; for z<2 additionally writes vs=eta*u, a0=soft
#define MODE_LCA   1   // fused LCA prox epilogue (z: 0=q, 1=k); writes tf32-rounded a
#define MODE_SCORE 2   // triangular grid decode (blockIdx.x = linear lower-tri tile)
#define MODE_PV    3   // causal K-limit; writes tf32-rounded C
#define MODE_PLAIN 4   // plain GEMM with alpha

#define NTHR 512
#define BK   32
#define STRD 40                        // floats per smem row (LDS.64 conflict-free)
#define TILE_SM (128 * STRD)           // 5120 floats per operand tile
#define STAGE_FL (2 * TILE_SM)         // A + B per stage
#define NSTAGE 4
#define GSMEM_BYTES (NSTAGE * STAGE_FL * 4)   // 163840 B

template <int MODE>
__global__ void __launch_bounds__(NTHR, 1)
mm_tf32(const float* __restrict__ A, const float* __restrict__ Bm, float* __restrict__ C,
        int K, int ldA, int ldB, int ldC, float alpha,
        long sA, long sB, long sC,
        const float* __restrict__ U, float* __restrict__ Vst, float* __restrict__ Aux,
        const float* __restrict__ llq, const float* __restrict__ llk)
{
    int r0, c0;
    if (MODE == MODE_SCORE) {
        const int t = blockIdx.x;                 // t = by*(by+1)/2 + bx, bx<=by
        int by = (int)((sqrtf(8.f * t + 1.f) - 1.f) * 0.5f);
        while ((by + 1) * (by + 2) / 2 <= t) by++;
        while (by * (by + 1) / 2 > t) by--;
        const int bx = t - by * (by + 1) / 2;
        r0 = by * 128; c0 = bx * 128;
    } else {
        r0 = blockIdx.y * 128;
        c0 = blockIdx.x * 128;
    }

    const long bz = blockIdx.z;
    A  += bz * sA;
    Bm += bz * sB;
    C  += bz * sC;

    extern __shared__ uint32_t sm[];

    const int tid  = threadIdx.x;
    const int lane = tid & 31;
    const int wid  = tid >> 5;          // 0..15
    const int wm   = (wid >> 2) * 32;   // warp row offset (0,32,64,96)
    const int wn   = (wid & 3) * 32;    // warp col offset (0,32,64,96)
    const int lr   = lane >> 2;         // 0..7
    const int lc   = lane & 3;          // 0..3

    const int kmax = (MODE == MODE_PV) ? min(K, r0 + 128) : K;
    const int nch  = kmax / BK;         // >= 4 for all uses

    float acc[2][4][4];
#pragma unroll
    for (int i = 0; i < 2; i++)
#pragma unroll
        for (int j = 0; j < 4; j++)
#pragma unroll
            for (int e = 0; e < 4; e++) acc[i][j][e] = 0.f;

    auto issue = [&](int cc) {
        const int stg = cc & (NSTAGE - 1);
        const float* Ac = A  + (long)r0 * ldA + cc * BK;
        const float* Bc = Bm + (long)c0 * ldB + cc * BK;
        const uint32_t ab = smem_u32(sm + stg * STAGE_FL);
        const uint32_t bb = ab + TILE_SM * 4;
#pragma unroll
        for (int i = 0; i < 2; i++) {           // 1024 16B slots, 512 threads
            const int idx = tid + i * NTHR;
            const int row = idx >> 3, c4 = idx & 7;
            cp_async16(ab + (uint32_t)(row * STRD + c4 * 4) * 4, Ac + (long)row * ldA + c4 * 4);
            cp_async16(bb + (uint32_t)(row * STRD + c4 * 4) * 4, Bc + (long)row * ldB + c4 * 4);
        }
        CP_COMMIT();
    };

    issue(0); issue(1); issue(2);               // nch >= 4 everywhere
    for (int c = 0; c < nch; c++) {
        const int rem = nch - 1 - c;            // newer groups still legitimately in flight
        if (rem >= 2)      CP_WAIT2();
        else if (rem == 1) CP_WAIT1();
        else               CP_WAIT0();
        __syncthreads();                        // frees stage (c-1)&3 == (c+3)&3
        if (c + 3 < nch) issue(c + 3);

        const uint32_t* Ab = sm + (c & (NSTAGE - 1)) * STAGE_FL;
        const uint32_t* Bb = Ab + TILE_SM;
#pragma unroll
        for (int o = 0; o < 4; o++) {
            const int koff = o * 8 + lc * 2;
            uint32_t af[2][4], bf[4][2];
#pragma unroll
            for (int mt = 0; mt < 2; mt++) {
                const uint2 lo = *(const uint2*)(Ab + (wm + mt * 16 + lr) * STRD + koff);
                const uint2 hi = *(const uint2*)(Ab + (wm + mt * 16 + lr + 8) * STRD + koff);
                af[mt][0] = lo.x;  af[mt][2] = lo.y;
                af[mt][1] = hi.x;  af[mt][3] = hi.y;
            }
#pragma unroll
            for (int nt = 0; nt < 4; nt++) {
                const uint2 bv = *(const uint2*)(Bb + (wn + nt * 8 + lr) * STRD + koff);
                bf[nt][0] = bv.x;  bf[nt][1] = bv.y;
            }
#pragma unroll
            for (int mt = 0; mt < 2; mt++)
#pragma unroll
                for (int nt = 0; nt < 4; nt++)
                    mma_tf32(acc[mt][nt], af[mt], bf[nt]);
        }
    }

    // ---------------- epilogue ----------------
    float lam = 0.f;
    if (MODE == MODE_LCA || (MODE == MODE_QKV && bz < 2))
        lam = expf(bz == 0 ? *llq : *llk);
#pragma unroll
    for (int mt = 0; mt < 2; mt++) {
#pragma unroll
        for (int h = 0; h < 2; h++) {
            const int row = r0 + wm + mt * 16 + lr + h * 8;
#pragma unroll
            for (int nt = 0; nt < 4; nt++) {
                const int col = c0 + wn + nt * 8 + lc * 2;
                const long idx = (long)row * ldC + col;
                float x0 = acc[mt][nt][h * 2 + 0];
                float x1 = acc[mt][nt][h * 2 + 1];
                if (MODE == MODE_LCA) {
                    float2 u2 = *(const float2*)(U + bz * sC + idx);
                    float2 v2 = *(const float2*)(Vst + bz * sC + idx);
                    float2 vn, o2;
                    vn.x = v2.x + ETA_C * (u2.x - v2.x - x0);
                    vn.y = v2.y + ETA_C * (u2.y - v2.y - x1);
                    *(float2*)(Vst + bz * sC + idx) = vn;
                    float s;
                    s = fabsf(vn.x) - lam; o2.x = (s > 0.f) ? rtf(copysignf(s, vn.x)) : 0.f;
                    s = fabsf(vn.y) - lam; o2.y = (s > 0.f) ? rtf(copysignf(s, vn.y)) : 0.f;
                    *(float2*)(C + idx) = o2;
                } else if (MODE == MODE_QKV) {
                    *(float2*)(C + idx) = make_float2(x0, x1);       // u (fp32)
                    if (bz < 2) {                                    // fused LCA iter 1
                        float2 vn = make_float2(ETA_C * x0, ETA_C * x1);
                        *(float2*)(Vst + bz * sC + idx) = vn;
                        float s; float2 a2;
                        s = fabsf(vn.x) - lam; a2.x = (s > 0.f) ? rtf(copysignf(s, vn.x)) : 0.f;
                        s = fabsf(vn.y) - lam; a2.y = (s > 0.f) ? rtf(copysignf(s, vn.y)) : 0.f;
                        *(float2*)(Aux + bz * sC + idx) = a2;
                    }
                } else if (MODE == MODE_PV) {
                    *(float2*)(C + idx) = make_float2(rtf(x0), rtf(x1));   // feeds final GEMM
                } else {                                              // SCORE / PLAIN
                    *(float2*)(C + idx) = make_float2(alpha * x0, alpha * x1);
                }
            }
        }
    }
}

// ---------------- small kernels ----------------
__global__ void round_copy(const float* __restrict__ in, float* __restrict__ out)
{
    const long i = ((long)blockIdx.x * blockDim.x + threadIdx.x) * 4;
    float4 v = *(const float4*)(in + i);
    v.x = rtf(v.x); v.y = rtf(v.y); v.z = rtf(v.z); v.w = rtf(v.w);
    *(float4*)(out + i) = v;
}

__global__ void symzero2(const float* __restrict__ Gq, const float* __restrict__ Gk,
                         float* __restrict__ Gs)
{
    const long idx = (long)blockIdx.x * blockDim.x + threadIdx.x;
    const long e = idx & (DD - 1);
    const float* G = (idx < DD) ? Gq : Gk;
    const int i = (int)(e / D_SZ), j = (int)(e % D_SZ);
    Gs[idx] = (i == j) ? 0.f : rtf(0.5f * (G[e] + G[(long)j * D_SZ + i]));
}

// V [B][T][D] -> Vt [B][D][T], tf32-rounded
__global__ void transpose_bt(const float* __restrict__ in, float* __restrict__ out)
{
    __shared__ float t[32][33];
    const int b = blockIdx.z;
    const int t0 = blockIdx.x * 32, d0 = blockIdx.y * 32;
    in  += (long)b * T_SZ * D_SZ;
    out += (long)b * T_SZ * D_SZ;
    const int x = threadIdx.x, y = threadIdx.y;
#pragma unroll
    for (int i = 0; i < 32; i += 8)
        t[y + i][x] = in[(long)(t0 + y + i) * D_SZ + d0 + x];
    __syncthreads();
#pragma unroll
    for (int i = 0; i < 32; i += 8)
        out[(long)(d0 + y + i) * T_SZ + t0 + x] = rtf(t[x][y + i]);
}

__global__ void softmax_causal(float* __restrict__ S)
{
    const int i = blockIdx.x;
    const int b = blockIdx.y;
    float* row = S + ((long)b * T_SZ + i) * T_SZ;
    const int tid = threadIdx.x;
    const int n = i + 1;
    __shared__ float red[256];

    float mx = -INFINITY;
    for (int j = tid; j < n; j += 256) mx = fmaxf(mx, row[j]);
    red[tid] = mx;
    __syncthreads();
    for (int s = 128; s > 0; s >>= 1) {
        if (tid < s) red[tid] = fmaxf(red[tid], red[tid + s]);
        __syncthreads();
    }
    mx = red[0];
    __syncthreads();

    float sum = 0.f;
    for (int j = tid; j < n; j += 256) {
        float e = expf(row[j] - mx);
        row[j] = e;
        sum += e;
    }
    red[tid] = sum;
    __syncthreads();
    for (int s = 128; s > 0; s >>= 1) {
        if (tid < s) red[tid] += red[tid + s];
        __syncthreads();
    }
    const float inv = 1.f / red[0];
    for (int j = tid; j < n; j += 256) row[j] = rtf(row[j] * inv);   // feeds PV GEMM
    for (int j = n + tid; j < T_SZ; j += 256) row[j] = 0.f;
}

// ---------------- launch ----------------
extern "C" void kernel_launch(void* const* d_in, const int* in_sizes, int n_in,
                              void* d_out, int out_size)
{
    const float* x        = (const float*)d_in[0];
    const float* W_qkv    = (const float*)d_in[1];
    const float* W_out    = (const float*)d_in[2];
    const float* Gq_raw   = (const float*)d_in[3];
    const float* loglam_q = (const float*)d_in[4];
    const float* Gk_raw   = (const float*)d_in[5];
    const float* loglam_k = (const float*)d_in[6];
    float* out = (float*)d_out;
    (void)in_sizes; (void)n_in; (void)out_size;

    float *u3, *vt, *vs, *abb, *G2, *S, *o, *xr, *wqr, *wor;
    cudaGetSymbolAddress((void**)&u3,  g_u3);
    cudaGetSymbolAddress((void**)&vt,  g_vt);
    cudaGetSymbolAddress((void**)&vs,  g_vs);
    cudaGetSymbolAddress((void**)&abb, g_ab);
    cudaGetSymbolAddress((void**)&G2,  g_G2);
    cudaGetSymbolAddress((void**)&S,   g_S);
    cudaGetSymbolAddress((void**)&o,   g_o);
    cudaGetSymbolAddress((void**)&xr,  g_xr);
    cudaGetSymbolAddress((void**)&wqr, g_wqkvr);
    cudaGetSymbolAddress((void**)&wor, g_woutr);

    cudaFuncSetAttribute(mm_tf32<MODE_QKV>,   cudaFuncAttributeMaxDynamicSharedMemorySize, GSMEM_BYTES);
    cudaFuncSetAttribute(mm_tf32<MODE_LCA>,   cudaFuncAttributeMaxDynamicSharedMemorySize, GSMEM_BYTES);
    cudaFuncSetAttribute(mm_tf32<MODE_SCORE>, cudaFuncAttributeMaxDynamicSharedMemorySize, GSMEM_BYTES);
    cudaFuncSetAttribute(mm_tf32<MODE_PV>,    cudaFuncAttributeMaxDynamicSharedMemorySize, GSMEM_BYTES);
    cudaFuncSetAttribute(mm_tf32<MODE_PLAIN>, cudaFuncAttributeMaxDynamicSharedMemorySize, GSMEM_BYTES);

    float* ab[2] = { abb, abb + 2 * MD };
    float* vvv = u3 + 2 * MD;

    const dim3 thr(256);
    const dim3 gthr(NTHR);
    const long TD = (long)T_SZ * D_SZ;
    const long TT = (long)T_SZ * T_SZ;

    // 0) pre-round raw GEMM inputs to tf32
    round_copy<<<(unsigned)(MD / 1024), thr>>>(x, xr);
    round_copy<<<(unsigned)(3 * DD / 1024), thr>>>(W_qkv, wqr);
    round_copy<<<(unsigned)(DD / 1024), thr>>>(W_out, wor);

    // 1) symmetrize + zero-diag both G's (tf32-rounded)
    symzero2<<<(unsigned)(2 * DD / 256), thr>>>(Gq_raw, Gk_raw, G2);

    // 2) QKV projections + fused LCA iteration 1 (z<2 writes vs, a0)
    {
        dim3 g(D_SZ / 128, M_SZ / 128, 3);
        mm_tf32<MODE_QKV><<<g, gthr, GSMEM_BYTES>>>(xr, wqr, u3, D_SZ, D_SZ, D_SZ, D_SZ, 1.f,
                                                    0, DD, MD, nullptr, vs, ab[0],
                                                    loglam_q, loglam_k);
    }

    // 3) transpose V (tf32-rounded)
    {
        dim3 g(T_SZ / 32, D_SZ / 32, B_SZ);
        transpose_bt<<<g, dim3(32, 8)>>>(vvv, vt);
    }

    // 4) LCA iterations 2..10: fused a@G + prox, q+k merged over z
    {
        dim3 g(D_SZ / 128, M_SZ / 128, 2);
        int cur = 0;
        for (int it = 0; it < LCA_GEMM_ITERS; it++) {
            mm_tf32<MODE_LCA><<<g, gthr, GSMEM_BYTES>>>(ab[cur], G2, ab[cur ^ 1],
                                                        D_SZ, D_SZ, D_SZ, D_SZ, 1.f,
                                                        MD, DD, MD, u3, vs, nullptr,
                                                        loglam_q, loglam_k);
            cur ^= 1;
        }
    }
    float* qf = ab[1];
    float* kf = ab[1] + MD;

    // 5) scores S = q k^T / 32, triangular grid (136 live tiles x batch)
    {
        dim3 g(136, 1, B_SZ);
        mm_tf32<MODE_SCORE><<<g, gthr, GSMEM_BYTES>>>(qf, kf, S, D_SZ, D_SZ, D_SZ, T_SZ, 0.03125f,
                                                      TD, TD, TT, nullptr, nullptr, nullptr,
                                                      nullptr, nullptr);
    }

    // 6) causal softmax (in place; rounds probs, zeroes masked tail)
    {
        dim3 g(T_SZ, B_SZ);
        softmax_causal<<<g, thr>>>(S);
    }

    // 7) o = P @ V (NT against Vt, causal K-limit); o tf32-rounded
    {
        dim3 g(D_SZ / 128, T_SZ / 128, B_SZ);
        mm_tf32<MODE_PV><<<g, gthr, GSMEM_BYTES>>>(S, vt, o, T_SZ, T_SZ, T_SZ, D_SZ, 1.f,
                                                   TT, TD, TD, nullptr, nullptr, nullptr,
                                                   nullptr, nullptr);
    }

    // 8) out = o @ W_out^T (fp32 output)
    {
        dim3 g(D_SZ / 128, M_SZ / 128, 1);
        mm_tf32<MODE_PLAIN><<<g, gthr, GSMEM_BYTES>>>(o, wor, out, D_SZ, D_SZ, D_SZ, D_SZ, 1.f,
                                                      0, 0, 0, nullptr, nullptr, nullptr,
                                                      nullptr, nullptr);
    }
}

// round 10
// speedup vs baseline: 1.4424x; 1.4424x over previous
#include <cuda_runtime.h>
#include <cstdint>
#include <math.h>

// ---------------- problem constants ----------------
#define B_SZ 4
#define T_SZ 2048
#define D_SZ 1024
#define M_SZ (B_SZ * T_SZ)
#define MD   ((long)M_SZ * D_SZ)
#define DD   ((long)D_SZ * D_SZ)
#define ETA_C 0.1f
#define LCA_SPARSE_ITERS 2   // GEMM-iterations done sparsely (a nearly empty)
#define LCA_DENSE_ITERS  7   // remaining dense tensor-core iterations

// ---------------- scratch (device globals; no allocation) ----------------
__device__ float g_u3[3 * M_SZ * D_SZ];      // u_q, u_k, v (fp32; z-indexed)
__device__ float g_vt[M_SZ * D_SZ];          // V^T per batch [B][D][T] (tf32-rounded)
__device__ float g_vs[2 * M_SZ * D_SZ];      // LCA v-state (fp32)
__device__ float g_ab[2][2 * M_SZ * D_SZ];   // LCA codes ping-pong x (q,k) (tf32-rounded)
__device__ float g_G2[2 * D_SZ * D_SZ];      // sym zero-diag Gq,Gk (tf32-rounded)
__device__ float g_S[(size_t)B_SZ * T_SZ * T_SZ];   // scores / probs
__device__ float g_o[M_SZ * D_SZ];           // attention out (tf32-rounded)
__device__ float g_xr[M_SZ * D_SZ];          // x rounded
__device__ float g_wqkvr[3 * D_SZ * D_SZ];   // W_qkv rounded
__device__ float g_woutr[D_SZ * D_SZ];       // W_out rounded

// ---------------- helpers ----------------
__device__ __forceinline__ uint32_t smem_u32(const void* p) {
    uint32_t a;
    asm("{ .reg .u64 t; cvta.to.shared.u64 t, %1; cvt.u32.u64 %0, t; }" : "=r"(a) : "l"(p));
    return a;
}
__device__ __forceinline__ void cp_async16(uint32_t dst, const void* src) {
    asm volatile("cp.async.cg.shared.global [%0], [%1], 16;" :: "r"(dst), "l"(src));
}
#define CP_COMMIT() asm volatile("cp.async.commit_group;" ::: "memory")
#define CP_WAIT1()  asm volatile("cp.async.wait_group 1;" ::: "memory")
#define CP_WAIT0()  asm volatile("cp.async.wait_group 0;" ::: "memory")

__device__ __forceinline__ uint32_t f2tf32(float f) {
    uint32_t r;
    asm("cvt.rna.tf32.f32 %0, %1;" : "=r"(r) : "f"(f));
    return r;
}
__device__ __forceinline__ float rtf(float f) { return __uint_as_float(f2tf32(f)); }

__device__ __forceinline__ void mma_tf32(float* c, const uint32_t* a, const uint32_t* b) {
    asm volatile(
        "mma.sync.aligned.m16n8k8.row.col.f32.tf32.tf32.f32 "
        "{%0,%1,%2,%3}, {%4,%5,%6,%7}, {%8,%9}, {%0,%1,%2,%3};"
        : "+f"(c[0]), "+f"(c[1]), "+f"(c[2]), "+f"(c[3])
        : "r"(a[0]), "r"(a[1]), "r"(a[2]), "r"(a[3]), "r"(b[0]), "r"(b[1]));
}

// ---------------- GEMM (NT): C[m,n] = alpha * sum_k A[m,k]*B[n,k] ----------------
// R5-proven shape: 128x128 CTA tile, 8 warps of 64x32, 2 CTAs/SM, 2-stage
// cp.async pipeline with issue-then-WAIT1 and two barriers per chunk.
// Inputs pre-rounded tf32; k-permuted layout for uint2 fragment loads.
#define MODE_QKV   0   // plain GEMM; for z<2 additionally writes vs=eta*u, a0=soft
#define MODE_LCA   1   // fused LCA prox epilogue (z: 0=q, 1=k); writes tf32-rounded a
#define MODE_SCORE 2   // triangular grid decode (blockIdx.x = linear lower-tri tile)
#define MODE_PV    3   // causal K-limit; writes tf32-rounded C
#define MODE_PLAIN 4   // plain GEMM with alpha

#define BK   32
#define STRD 40                       // floats per smem row (LDS.64 conflict-free)
#define TILE_SM (128 * STRD)
#define GSMEM_BYTES (4 * TILE_SM * 4) // 2 A + 2 B buffers = 81920 B

template <int MODE>
__global__ void __launch_bounds__(256, 2)
mm_tf32(const float* __restrict__ A, const float* __restrict__ Bm, float* __restrict__ C,
        int K, int ldA, int ldB, int ldC, float alpha,
        long sA, long sB, long sC,
        const float* __restrict__ U, float* __restrict__ Vst, float* __restrict__ Aux,
        const float* __restrict__ llq, const float* __restrict__ llk)
{
    int r0, c0;
    if (MODE == MODE_SCORE) {
        const int t = blockIdx.x;                 // t = by*(by+1)/2 + bx, bx<=by
        int by = (int)((sqrtf(8.f * t + 1.f) - 1.f) * 0.5f);
        while ((by + 1) * (by + 2) / 2 <= t) by++;
        while (by * (by + 1) / 2 > t) by--;
        const int bx = t - by * (by + 1) / 2;
        r0 = by * 128; c0 = bx * 128;
    } else {
        r0 = blockIdx.y * 128;
        c0 = blockIdx.x * 128;
    }

    const long bz = blockIdx.z;
    A  += bz * sA;
    Bm += bz * sB;
    C  += bz * sC;

    extern __shared__ uint32_t sm[];
    uint32_t* Asb[2] = { sm,               sm + TILE_SM };
    uint32_t* Bsb[2] = { sm + 2 * TILE_SM, sm + 3 * TILE_SM };

    const int tid  = threadIdx.x;
    const int lane = tid & 31;
    const int wid  = tid >> 5;
    const int wm   = (wid >> 2) * 64;
    const int wn   = (wid & 3) * 32;
    const int lr   = lane >> 2;         // 0..7
    const int lc   = lane & 3;          // 0..3

    const int kmax = (MODE == MODE_PV) ? min(K, r0 + 128) : K;
    const int nch  = kmax / BK;

    float acc[4][4][4];
#pragma unroll
    for (int i = 0; i < 4; i++)
#pragma unroll
        for (int j = 0; j < 4; j++)
#pragma unroll
            for (int e = 0; e < 4; e++) acc[i][j][e] = 0.f;

    auto issue = [&](int c) {
        const int buf = c & 1;
        const float* Ac = A  + (long)r0 * ldA + c * BK;
        const float* Bc = Bm + (long)c0 * ldB + c * BK;
        const uint32_t ab = smem_u32(Asb[buf]);
        const uint32_t bb = smem_u32(Bsb[buf]);
#pragma unroll
        for (int i = 0; i < 4; i++) {
            const int idx = tid + i * 256;
            const int row = idx >> 3, c4 = idx & 7;
            cp_async16(ab + (uint32_t)(row * STRD + c4 * 4) * 4, Ac + (long)row * ldA + c4 * 4);
            cp_async16(bb + (uint32_t)(row * STRD + c4 * 4) * 4, Bc + (long)row * ldB + c4 * 4);
        }
        CP_COMMIT();
    };

    issue(0);
    for (int c = 0; c < nch; c++) {
        if (c + 1 < nch) { issue(c + 1); CP_WAIT1(); }
        else             { CP_WAIT0(); }
        __syncthreads();

        const uint32_t* Ab = Asb[c & 1];
        const uint32_t* Bb = Bsb[c & 1];
#pragma unroll
        for (int o = 0; o < 4; o++) {
            const int koff = o * 8 + lc * 2;
            uint32_t af[4][4], bf[4][2];
#pragma unroll
            for (int mt = 0; mt < 4; mt++) {
                const uint2 lo = *(const uint2*)(Ab + (wm + mt * 16 + lr) * STRD + koff);
                const uint2 hi = *(const uint2*)(Ab + (wm + mt * 16 + lr + 8) * STRD + koff);
                af[mt][0] = lo.x;  af[mt][2] = lo.y;
                af[mt][1] = hi.x;  af[mt][3] = hi.y;
            }
#pragma unroll
            for (int nt = 0; nt < 4; nt++) {
                const uint2 bv = *(const uint2*)(Bb + (wn + nt * 8 + lr) * STRD + koff);
                bf[nt][0] = bv.x;  bf[nt][1] = bv.y;
            }
#pragma unroll
            for (int mt = 0; mt < 4; mt++)
#pragma unroll
                for (int nt = 0; nt < 4; nt++)
                    mma_tf32(acc[mt][nt], af[mt], bf[nt]);
        }
        __syncthreads();
    }

    // ---------------- epilogue ----------------
    float lam = 0.f;
    if (MODE == MODE_LCA || (MODE == MODE_QKV && bz < 2))
        lam = expf(bz == 0 ? *llq : *llk);
#pragma unroll
    for (int mt = 0; mt < 4; mt++) {
#pragma unroll
        for (int h = 0; h < 2; h++) {
            const int row = r0 + wm + mt * 16 + lr + h * 8;
#pragma unroll
            for (int nt = 0; nt < 4; nt++) {
                const int col = c0 + wn + nt * 8 + lc * 2;
                const long idx = (long)row * ldC + col;
                float x0 = acc[mt][nt][h * 2 + 0];
                float x1 = acc[mt][nt][h * 2 + 1];
                if (MODE == MODE_LCA) {
                    float2 u2 = *(const float2*)(U + bz * sC + idx);
                    float2 v2 = *(const float2*)(Vst + bz * sC + idx);
                    float2 vn, o2;
                    vn.x = v2.x + ETA_C * (u2.x - v2.x - x0);
                    vn.y = v2.y + ETA_C * (u2.y - v2.y - x1);
                    *(float2*)(Vst + bz * sC + idx) = vn;
                    float s;
                    s = fabsf(vn.x) - lam; o2.x = (s > 0.f) ? rtf(copysignf(s, vn.x)) : 0.f;
                    s = fabsf(vn.y) - lam; o2.y = (s > 0.f) ? rtf(copysignf(s, vn.y)) : 0.f;
                    *(float2*)(C + idx) = o2;
                } else if (MODE == MODE_QKV) {
                    *(float2*)(C + idx) = make_float2(x0, x1);       // u (fp32)
                    if (bz < 2) {                                    // fused LCA iter 1
                        float2 vn = make_float2(ETA_C * x0, ETA_C * x1);
                        *(float2*)(Vst + bz * sC + idx) = vn;
                        float s; float2 a2;
                        s = fabsf(vn.x) - lam; a2.x = (s > 0.f) ? rtf(copysignf(s, vn.x)) : 0.f;
                        s = fabsf(vn.y) - lam; a2.y = (s > 0.f) ? rtf(copysignf(s, vn.y)) : 0.f;
                        *(float2*)(Aux + bz * sC + idx) = a2;
                    }
                } else if (MODE == MODE_PV) {
                    *(float2*)(C + idx) = make_float2(rtf(x0), rtf(x1));   // feeds final GEMM
                } else {                                              // SCORE / PLAIN
                    *(float2*)(C + idx) = make_float2(alpha * x0, alpha * x1);
                }
            }
        }
    }
}

// ---------------- sparse LCA iteration: warp per row ----------------
// a_in is extremely sparse (early LCA iterations). Computes row m of a_in @ G
// by gathering G[k,:] only for nonzero a_in[m,k], then applies the same fused
// prox update. Rows 0..M-1 are q (G=G2[0], lam=llq); rows M.. are k.
__global__ void __launch_bounds__(256, 4)
lca_sparse(const float* __restrict__ a_in, const float* __restrict__ G2,
           const float* __restrict__ U, float* __restrict__ Vst,
           float* __restrict__ a_out,
           const float* __restrict__ llq, const float* __restrict__ llk)
{
    const long row  = ((long)blockIdx.x * blockDim.x + threadIdx.x) >> 5;  // 0..2M-1
    const int  lane = threadIdx.x & 31;
    const int  half = (row >= M_SZ);
    const float* G  = G2 + (long)half * DD;
    const float lam = expf(half ? *llk : *llq);

    const float* arow = a_in + row * D_SZ;

    // accumulator covers cols lane*4 + 128*j + i  (j=0..7, i=0..3)
    float acc[8][4];
#pragma unroll
    for (int j = 0; j < 8; j++)
#pragma unroll
        for (int i = 0; i < 4; i++) acc[j][i] = 0.f;

#pragma unroll
    for (int j = 0; j < 8; j++) {
        const float4 av = *(const float4*)(arow + lane * 4 + 128 * j);
        const float vals[4] = { av.x, av.y, av.z, av.w };
#pragma unroll
        for (int i = 0; i < 4; i++) {
            unsigned m = __ballot_sync(0xFFFFFFFFu, vals[i] != 0.f);
            while (m) {
                const int s = __ffs(m) - 1;
                m &= m - 1;
                const float aval = __shfl_sync(0xFFFFFFFFu, vals[i], s);
                const int k = s * 4 + 128 * j + i;
                const float* Gr = G + (long)k * D_SZ + lane * 4;
#pragma unroll
                for (int jj = 0; jj < 8; jj++) {
                    const float4 gv = *(const float4*)(Gr + 128 * jj);
                    acc[jj][0] += aval * gv.x;
                    acc[jj][1] += aval * gv.y;
                    acc[jj][2] += aval * gv.z;
                    acc[jj][3] += aval * gv.w;
                }
            }
        }
    }

    // fused prox update (identical arithmetic to the dense LCA epilogue)
    const float* urow = U + row * D_SZ;
    float* vrow = Vst + row * D_SZ;
    float* orow = a_out + row * D_SZ;
#pragma unroll
    for (int j = 0; j < 8; j++) {
        const int c = lane * 4 + 128 * j;
        const float4 uv = *(const float4*)(urow + c);
        const float4 vv = *(const float4*)(vrow + c);
        float4 vn, o4;
        vn.x = vv.x + ETA_C * (uv.x - vv.x - acc[j][0]);
        vn.y = vv.y + ETA_C * (uv.y - vv.y - acc[j][1]);
        vn.z = vv.z + ETA_C * (uv.z - vv.z - acc[j][2]);
        vn.w = vv.w + ETA_C * (uv.w - vv.w - acc[j][3]);
        *(float4*)(vrow + c) = vn;
        float s;
        s = fabsf(vn.x) - lam; o4.x = (s > 0.f) ? rtf(copysignf(s, vn.x)) : 0.f;
        s = fabsf(vn.y) - lam; o4.y = (s > 0.f) ? rtf(copysignf(s, vn.y)) : 0.f;
        s = fabsf(vn.z) - lam; o4.z = (s > 0.f) ? rtf(copysignf(s, vn.z)) : 0.f;
        s = fabsf(vn.w) - lam; o4.w = (s > 0.f) ? rtf(copysignf(s, vn.w)) : 0.f;
        *(float4*)(orow + c) = o4;
    }
}

// ---------------- small kernels ----------------
__global__ void round_copy(const float* __restrict__ in, float* __restrict__ out)
{
    const long i = ((long)blockIdx.x * blockDim.x + threadIdx.x) * 4;
    float4 v = *(const float4*)(in + i);
    v.x = rtf(v.x); v.y = rtf(v.y); v.z = rtf(v.z); v.w = rtf(v.w);
    *(float4*)(out + i) = v;
}

__global__ void symzero2(const float* __restrict__ Gq, const float* __restrict__ Gk,
                         float* __restrict__ Gs)
{
    const long idx = (long)blockIdx.x * blockDim.x + threadIdx.x;
    const long e = idx & (DD - 1);
    const float* G = (idx < DD) ? Gq : Gk;
    const int i = (int)(e / D_SZ), j = (int)(e % D_SZ);
    Gs[idx] = (i == j) ? 0.f : rtf(0.5f * (G[e] + G[(long)j * D_SZ + i]));
}

// V [B][T][D] -> Vt [B][D][T], tf32-rounded
__global__ void transpose_bt(const float* __restrict__ in, float* __restrict__ out)
{
    __shared__ float t[32][33];
    const int b = blockIdx.z;
    const int t0 = blockIdx.x * 32, d0 = blockIdx.y * 32;
    in  += (long)b * T_SZ * D_SZ;
    out += (long)b * T_SZ * D_SZ;
    const int x = threadIdx.x, y = threadIdx.y;
#pragma unroll
    for (int i = 0; i < 32; i += 8)
        t[y + i][x] = in[(long)(t0 + y + i) * D_SZ + d0 + x];
    __syncthreads();
#pragma unroll
    for (int i = 0; i < 32; i += 8)
        out[(long)(d0 + y + i) * T_SZ + t0 + x] = rtf(t[x][y + i]);
}

__global__ void softmax_causal(float* __restrict__ S)
{
    const int i = blockIdx.x;
    const int b = blockIdx.y;
    float* row = S + ((long)b * T_SZ + i) * T_SZ;
    const int tid = threadIdx.x;
    const int n = i + 1;
    __shared__ float red[256];

    float mx = -INFINITY;
    for (int j = tid; j < n; j += 256) mx = fmaxf(mx, row[j]);
    red[tid] = mx;
    __syncthreads();
    for (int s = 128; s > 0; s >>= 1) {
        if (tid < s) red[tid] = fmaxf(red[tid], red[tid + s]);
        __syncthreads();
    }
    mx = red[0];
    __syncthreads();

    float sum = 0.f;
    for (int j = tid; j < n; j += 256) {
        float e = expf(row[j] - mx);
        row[j] = e;
        sum += e;
    }
    red[tid] = sum;
    __syncthreads();
    for (int s = 128; s > 0; s >>= 1) {
        if (tid < s) red[tid] += red[tid + s];
        __syncthreads();
    }
    const float inv = 1.f / red[0];
    for (int j = tid; j < n; j += 256) row[j] = rtf(row[j] * inv);   // feeds PV GEMM
    for (int j = n + tid; j < T_SZ; j += 256) row[j] = 0.f;
}

// ---------------- launch ----------------
extern "C" void kernel_launch(void* const* d_in, const int* in_sizes, int n_in,
                              void* d_out, int out_size)
{
    const float* x        = (const float*)d_in[0];
    const float* W_qkv    = (const float*)d_in[1];
    const float* W_out    = (const float*)d_in[2];
    const float* Gq_raw   = (const float*)d_in[3];
    const float* loglam_q = (const float*)d_in[4];
    const float* Gk_raw   = (const float*)d_in[5];
    const float* loglam_k = (const float*)d_in[6];
    float* out = (float*)d_out;
    (void)in_sizes; (void)n_in; (void)out_size;

    float *u3, *vt, *vs, *abb, *G2, *S, *o, *xr, *wqr, *wor;
    cudaGetSymbolAddress((void**)&u3,  g_u3);
    cudaGetSymbolAddress((void**)&vt,  g_vt);
    cudaGetSymbolAddress((void**)&vs,  g_vs);
    cudaGetSymbolAddress((void**)&abb, g_ab);
    cudaGetSymbolAddress((void**)&G2,  g_G2);
    cudaGetSymbolAddress((void**)&S,   g_S);
    cudaGetSymbolAddress((void**)&o,   g_o);
    cudaGetSymbolAddress((void**)&xr,  g_xr);
    cudaGetSymbolAddress((void**)&wqr, g_wqkvr);
    cudaGetSymbolAddress((void**)&wor, g_woutr);

    cudaFuncSetAttribute(mm_tf32<MODE_QKV>,   cudaFuncAttributeMaxDynamicSharedMemorySize, GSMEM_BYTES);
    cudaFuncSetAttribute(mm_tf32<MODE_LCA>,   cudaFuncAttributeMaxDynamicSharedMemorySize, GSMEM_BYTES);
    cudaFuncSetAttribute(mm_tf32<MODE_SCORE>, cudaFuncAttributeMaxDynamicSharedMemorySize, GSMEM_BYTES);
    cudaFuncSetAttribute(mm_tf32<MODE_PV>,    cudaFuncAttributeMaxDynamicSharedMemorySize, GSMEM_BYTES);
    cudaFuncSetAttribute(mm_tf32<MODE_PLAIN>, cudaFuncAttributeMaxDynamicSharedMemorySize, GSMEM_BYTES);

    float* ab[2] = { abb, abb + 2 * MD };
    float* vvv = u3 + 2 * MD;

    const dim3 thr(256);
    const long TD = (long)T_SZ * D_SZ;
    const long TT = (long)T_SZ * T_SZ;

    // 0) pre-round raw GEMM inputs to tf32
    round_copy<<<(unsigned)(MD / 1024), thr>>>(x, xr);
    round_copy<<<(unsigned)(3 * DD / 1024), thr>>>(W_qkv, wqr);
    round_copy<<<(unsigned)(DD / 1024), thr>>>(W_out, wor);

    // 1) symmetrize + zero-diag both G's (tf32-rounded)
    symzero2<<<(unsigned)(2 * DD / 256), thr>>>(Gq_raw, Gk_raw, G2);

    // 2) QKV projections + fused LCA iteration 1 (z<2 writes vs, a0)
    {
        dim3 g(D_SZ / 128, M_SZ / 128, 3);
        mm_tf32<MODE_QKV><<<g, thr, GSMEM_BYTES>>>(xr, wqr, u3, D_SZ, D_SZ, D_SZ, D_SZ, 1.f,
                                                   0, DD, MD, nullptr, vs, ab[0],
                                                   loglam_q, loglam_k);
    }

    // 3) transpose V (tf32-rounded)
    {
        dim3 g(T_SZ / 32, D_SZ / 32, B_SZ);
        transpose_bt<<<g, dim3(32, 8)>>>(vvv, vt);
    }

    // 4) LCA iterations 2..3: SPARSE (a is ~0% / ~1% dense here)
    int cur = 0;
    {
        const unsigned nwarp_cta = 8;                     // 256 thr
        const unsigned g = (unsigned)(2 * M_SZ / nwarp_cta);   // warp per row
        for (int it = 0; it < LCA_SPARSE_ITERS; it++) {
            lca_sparse<<<g, thr>>>(ab[cur], G2, u3, vs, ab[cur ^ 1], loglam_q, loglam_k);
            cur ^= 1;
        }
    }

    // 5) LCA iterations 4..10: dense fused a@G + prox, q+k merged over z
    {
        dim3 g(D_SZ / 128, M_SZ / 128, 2);
        for (int it = 0; it < LCA_DENSE_ITERS; it++) {
            mm_tf32<MODE_LCA><<<g, thr, GSMEM_BYTES>>>(ab[cur], G2, ab[cur ^ 1],
                                                       D_SZ, D_SZ, D_SZ, D_SZ, 1.f,
                                                       MD, DD, MD, u3, vs, nullptr,
                                                       loglam_q, loglam_k);
            cur ^= 1;
        }
    }
    float* qf = ab[cur];            // 2 sparse + 7 dense = 9 iters -> cur==1
    float* kf = ab[cur] + MD;

    // 6) scores S = q k^T / 32, triangular grid (136 live tiles x batch)
    {
        dim3 g(136, 1, B_SZ);
        mm_tf32<MODE_SCORE><<<g, thr, GSMEM_BYTES>>>(qf, kf, S, D_SZ, D_SZ, D_SZ, T_SZ, 0.03125f,
                                                     TD, TD, TT, nullptr, nullptr, nullptr,
                                                     nullptr, nullptr);
    }

    // 7) causal softmax (in place; rounds probs, zeroes masked tail)
    {
        dim3 g(T_SZ, B_SZ);
        softmax_causal<<<g, thr>>>(S);
    }

    // 8) o = P @ V (NT against Vt, causal K-limit); o tf32-rounded
    {
        dim3 g(D_SZ / 128, T_SZ / 128, B_SZ);
        mm_tf32<MODE_PV><<<g, thr, GSMEM_BYTES>>>(S, vt, o, T_SZ, T_SZ, T_SZ, D_SZ, 1.f,
                                                  TT, TD, TD, nullptr, nullptr, nullptr,
                                                  nullptr, nullptr);
    }

    // 9) out = o @ W_out^T (fp32 output)
    {
        dim3 g(D_SZ / 128, M_SZ / 128, 1);
        mm_tf32<MODE_PLAIN><<<g, thr, GSMEM_BYTES>>>(o, wor, out, D_SZ, D_SZ, D_SZ, D_SZ, 1.f,
                                                     0, 0, 0, nullptr, nullptr, nullptr,
                                                     nullptr, nullptr);
    }
}

// round 11
// speedup vs baseline: 2.3392x; 1.6217x over previous
#include <cuda_runtime.h>
#include <cuda_fp16.h>
#include <cstdint>
#include <math.h>

// ---------------- problem constants ----------------
#define B_SZ 4
#define T_SZ 2048
#define D_SZ 1024
#define M_SZ (B_SZ * T_SZ)
#define MD   ((long)M_SZ * D_SZ)
#define DD   ((long)D_SZ * D_SZ)
#define TT   ((long)T_SZ * T_SZ)
#define TD   ((long)T_SZ * D_SZ)
#define ETA_C 0.1f
#define LCA_SPARSE_ITERS 2
#define LCA_DENSE_ITERS  7

// ---------------- scratch (device globals; no allocation) ----------------
__device__ float  g_u3[3 * M_SZ * D_SZ];     // u_q, u_k, v (fp32)
__device__ __half g_vt[M_SZ * D_SZ];         // V^T per batch [B][D][T] (fp16)
__device__ float  g_vs[2 * M_SZ * D_SZ];     // LCA v-state (fp32)
__device__ __half g_ab[2][2 * M_SZ * D_SZ];  // LCA codes ping-pong x (q,k) (fp16)
__device__ __half g_G2[2 * D_SZ * D_SZ];     // sym zero-diag Gq,Gk (fp16)
__device__ float  g_S[(size_t)B_SZ * T_SZ * T_SZ];   // scores (fp32)
__device__ __half g_Ph[(size_t)B_SZ * T_SZ * T_SZ];  // probs (fp16)
__device__ __half g_o[M_SZ * D_SZ];          // attention out (fp16)
__device__ __half g_xr[M_SZ * D_SZ];         // x (fp16)
__device__ __half g_wqkvr[3 * D_SZ * D_SZ];  // W_qkv (fp16)
__device__ __half g_woutr[D_SZ * D_SZ];      // W_out (fp16)

// ---------------- helpers ----------------
__device__ __forceinline__ uint32_t smem_u32(const void* p) {
    uint32_t a;
    asm("{ .reg .u64 t; cvta.to.shared.u64 t, %1; cvt.u32.u64 %0, t; }" : "=r"(a) : "l"(p));
    return a;
}
__device__ __forceinline__ void cp_async16(uint32_t dst, const void* src) {
    asm volatile("cp.async.cg.shared.global [%0], [%1], 16;" :: "r"(dst), "l"(src));
}
#define CP_COMMIT() asm volatile("cp.async.commit_group;" ::: "memory")
#define CP_WAIT1()  asm volatile("cp.async.wait_group 1;" ::: "memory")
#define CP_WAIT0()  asm volatile("cp.async.wait_group 0;" ::: "memory")

__device__ __forceinline__ void mma_f16(float* c, const uint32_t* a, const uint32_t* b) {
    asm volatile(
        "mma.sync.aligned.m16n8k16.row.col.f32.f16.f16.f32 "
        "{%0,%1,%2,%3}, {%4,%5,%6,%7}, {%8,%9}, {%0,%1,%2,%3};"
        : "+f"(c[0]), "+f"(c[1]), "+f"(c[2]), "+f"(c[3])
        : "r"(a[0]), "r"(a[1]), "r"(a[2]), "r"(a[3]), "r"(b[0]), "r"(b[1]));
}
__device__ __forceinline__ uint32_t h2pack(float a, float b) {
    __half2 h = __floats2half2_rn(a, b);
    return *reinterpret_cast<uint32_t*>(&h);
}

// ---------------- GEMM (NT, fp16 in / fp32 acc): C = alpha * A B^T --------------
// R5/R10-proven shape: 128x128 CTA tile, 8 warps of 64x32, 2 CTAs/SM, 2-stage
// cp.async, issue-then-WAIT1, two barriers per chunk. BK=64 halves (128B rows,
// same smem bytes as the tf32 version but twice the k per chunk).
// Implicit k-relabel per 16-k group: smem pos 4lc+{0,1,2,3} <-> mma-k
// {2lc,2lc+1,2lc+8,2lc+9} (A and B consistent -> exact GEMM).
#define MODE_QKV   0   // C=u fp32; for z<2 also vs=eta*u, a0=soft (fp16)
#define MODE_LCA   1   // fused LCA prox; writes fp16 a
#define MODE_SCORE 2   // triangular-grid decode; writes fp32 S
#define MODE_PV    3   // causal K-limit; writes fp16 o
#define MODE_PLAIN 4   // writes fp32 out

#define BK   64                       // k per chunk (halves)
#define STRD 40                       // uint32 per smem row (160B)
#define TILE_U32 (128 * STRD)
#define GSMEM_BYTES (4 * TILE_U32 * 4)   // 2 A + 2 B stages = 81920 B

template <int MODE>
__global__ void __launch_bounds__(256, 2)
mm_f16(const __half* __restrict__ A, const __half* __restrict__ Bm, void* __restrict__ Cv,
       int K, int ldA, int ldB, int ldC, float alpha,
       long sA, long sB, long sC,
       const float* __restrict__ U, float* __restrict__ Vst, __half* __restrict__ Aux,
       const float* __restrict__ llq, const float* __restrict__ llk)
{
    int r0, c0;
    if (MODE == MODE_SCORE) {
        const int t = blockIdx.x;                 // t = by*(by+1)/2 + bx, bx<=by
        int by = (int)((sqrtf(8.f * t + 1.f) - 1.f) * 0.5f);
        while ((by + 1) * (by + 2) / 2 <= t) by++;
        while (by * (by + 1) / 2 > t) by--;
        const int bx = t - by * (by + 1) / 2;
        r0 = by * 128; c0 = bx * 128;
    } else {
        r0 = blockIdx.y * 128;
        c0 = blockIdx.x * 128;
    }

    const long bz = blockIdx.z;
    A  += bz * sA;
    Bm += bz * sB;

    extern __shared__ uint32_t sm[];
    uint32_t* Asb[2] = { sm,               sm + TILE_U32 };
    uint32_t* Bsb[2] = { sm + 2 * TILE_U32, sm + 3 * TILE_U32 };

    const int tid  = threadIdx.x;
    const int lane = tid & 31;
    const int wid  = tid >> 5;
    const int wm   = (wid >> 2) * 64;
    const int wn   = (wid & 3) * 32;
    const int lr   = lane >> 2;         // 0..7
    const int lc   = lane & 3;          // 0..3

    const int kmax = (MODE == MODE_PV) ? min(K, r0 + 128) : K;
    const int nch  = kmax / BK;

    float acc[4][4][4];
#pragma unroll
    for (int i = 0; i < 4; i++)
#pragma unroll
        for (int j = 0; j < 4; j++)
#pragma unroll
            for (int e = 0; e < 4; e++) acc[i][j][e] = 0.f;

    auto issue = [&](int c) {
        const int buf = c & 1;
        const __half* Ac = A  + (long)r0 * ldA + c * BK;
        const __half* Bc = Bm + (long)c0 * ldB + c * BK;
        const uint32_t ab = smem_u32(Asb[buf]);
        const uint32_t bb = smem_u32(Bsb[buf]);
#pragma unroll
        for (int i = 0; i < 4; i++) {
            const int idx = tid + i * 256;       // 1024 16B granules per tile
            const int row = idx >> 3, c4 = idx & 7;
            cp_async16(ab + (uint32_t)(row * 160 + c4 * 16), Ac + (long)row * ldA + c4 * 8);
            cp_async16(bb + (uint32_t)(row * 160 + c4 * 16), Bc + (long)row * ldB + c4 * 8);
        }
        CP_COMMIT();
    };

    issue(0);
    for (int c = 0; c < nch; c++) {
        if (c + 1 < nch) { issue(c + 1); CP_WAIT1(); }
        else             { CP_WAIT0(); }
        __syncthreads();

        const uint32_t* Ab = Asb[c & 1];
        const uint32_t* Bb = Bsb[c & 1];
#pragma unroll
        for (int g = 0; g < 4; g++) {            // four 16-k groups per chunk
            const int koff = g * 8 + lc * 2;     // uint32 offset within row
            uint32_t af[4][4], bf[4][2];
#pragma unroll
            for (int mt = 0; mt < 4; mt++) {
                const uint2 lo = *(const uint2*)(Ab + (wm + mt * 16 + lr) * STRD + koff);
                const uint2 hi = *(const uint2*)(Ab + (wm + mt * 16 + lr + 8) * STRD + koff);
                af[mt][0] = lo.x;  af[mt][2] = lo.y;
                af[mt][1] = hi.x;  af[mt][3] = hi.y;
            }
#pragma unroll
            for (int nt = 0; nt < 4; nt++) {
                const uint2 bv = *(const uint2*)(Bb + (wn + nt * 8 + lr) * STRD + koff);
                bf[nt][0] = bv.x;  bf[nt][1] = bv.y;
            }
#pragma unroll
            for (int mt = 0; mt < 4; mt++)
#pragma unroll
                for (int nt = 0; nt < 4; nt++)
                    mma_f16(acc[mt][nt], af[mt], bf[nt]);
        }
        __syncthreads();
    }

    // ---------------- epilogue ----------------
    float lam = 0.f;
    if (MODE == MODE_LCA || (MODE == MODE_QKV && bz < 2))
        lam = expf(bz == 0 ? *llq : *llk);
#pragma unroll
    for (int mt = 0; mt < 4; mt++) {
#pragma unroll
        for (int h = 0; h < 2; h++) {
            const int row = r0 + wm + mt * 16 + lr + h * 8;
#pragma unroll
            for (int nt = 0; nt < 4; nt++) {
                const int col = c0 + wn + nt * 8 + lc * 2;
                const long idx = (long)row * ldC + col;
                float x0 = acc[mt][nt][h * 2 + 0];
                float x1 = acc[mt][nt][h * 2 + 1];
                if (MODE == MODE_LCA) {
                    __half* Ch = (__half*)Cv + bz * sC;
                    float2 u2 = *(const float2*)(U + bz * sC + idx);
                    float2 v2 = *(const float2*)(Vst + bz * sC + idx);
                    float2 vn;
                    vn.x = v2.x + ETA_C * (u2.x - v2.x - x0);
                    vn.y = v2.y + ETA_C * (u2.y - v2.y - x1);
                    *(float2*)(Vst + bz * sC + idx) = vn;
                    float s, o0, o1;
                    s = fabsf(vn.x) - lam; o0 = (s > 0.f) ? copysignf(s, vn.x) : 0.f;
                    s = fabsf(vn.y) - lam; o1 = (s > 0.f) ? copysignf(s, vn.y) : 0.f;
                    *(uint32_t*)(Ch + idx) = h2pack(o0, o1);
                } else if (MODE == MODE_QKV) {
                    float* Cf = (float*)Cv + bz * sC;
                    *(float2*)(Cf + idx) = make_float2(x0, x1);      // u (fp32)
                    if (bz < 2) {                                    // fused LCA iter 1
                        float2 vn = make_float2(ETA_C * x0, ETA_C * x1);
                        *(float2*)(Vst + bz * sC + idx) = vn;
                        float s, o0, o1;
                        s = fabsf(vn.x) - lam; o0 = (s > 0.f) ? copysignf(s, vn.x) : 0.f;
                        s = fabsf(vn.y) - lam; o1 = (s > 0.f) ? copysignf(s, vn.y) : 0.f;
                        *(uint32_t*)(Aux + bz * sC + idx) = h2pack(o0, o1);
                    }
                } else if (MODE == MODE_PV) {
                    __half* Ch = (__half*)Cv + bz * sC;
                    *(uint32_t*)(Ch + idx) = h2pack(x0, x1);
                } else {  // SCORE / PLAIN -> fp32
                    float* Cf = (float*)Cv + bz * sC;
                    *(float2*)(Cf + idx) = make_float2(alpha * x0, alpha * x1);
                }
            }
        }
    }
}

// ---------------- sparse LCA iteration: warp per row (fp16 a, fp16 G) ----------
__global__ void __launch_bounds__(256, 4)
lca_sparse(const __half* __restrict__ a_in, const __half* __restrict__ G2,
           const float* __restrict__ U, float* __restrict__ Vst,
           __half* __restrict__ a_out,
           const float* __restrict__ llq, const float* __restrict__ llk)
{
    const long row  = ((long)blockIdx.x * blockDim.x + threadIdx.x) >> 5;
    const int  lane = threadIdx.x & 31;
    const int  half = (row >= M_SZ);
    const __half* G = G2 + (long)half * DD;
    const float lam = expf(half ? *llk : *llq);

    const __half* arow = a_in + row * D_SZ;

    float acc[8][4];
#pragma unroll
    for (int j = 0; j < 8; j++)
#pragma unroll
        for (int i = 0; i < 4; i++) acc[j][i] = 0.f;

#pragma unroll
    for (int j = 0; j < 8; j++) {
        const __half2* ap = (const __half2*)(arow + lane * 4 + 128 * j);
        const float2 f0 = __half22float2(ap[0]);
        const float2 f1 = __half22float2(ap[1]);
        const float vals[4] = { f0.x, f0.y, f1.x, f1.y };
#pragma unroll
        for (int i = 0; i < 4; i++) {
            unsigned m = __ballot_sync(0xFFFFFFFFu, vals[i] != 0.f);
            while (m) {
                const int s = __ffs(m) - 1;
                m &= m - 1;
                const float aval = __shfl_sync(0xFFFFFFFFu, vals[i], s);
                const int k = s * 4 + 128 * j + i;
                const __half* Gr = G + (long)k * D_SZ + lane * 4;
#pragma unroll
                for (int jj = 0; jj < 8; jj++) {
                    const __half2* gp = (const __half2*)(Gr + 128 * jj);
                    const float2 g0 = __half22float2(gp[0]);
                    const float2 g1 = __half22float2(gp[1]);
                    acc[jj][0] += aval * g0.x;
                    acc[jj][1] += aval * g0.y;
                    acc[jj][2] += aval * g1.x;
                    acc[jj][3] += aval * g1.y;
                }
            }
        }
    }

    const float* urow = U + row * D_SZ;
    float* vrow = Vst + row * D_SZ;
    __half* orow = a_out + row * D_SZ;
#pragma unroll
    for (int j = 0; j < 8; j++) {
        const int c = lane * 4 + 128 * j;
        const float4 uv = *(const float4*)(urow + c);
        const float4 vv = *(const float4*)(vrow + c);
        float4 vn;
        vn.x = vv.x + ETA_C * (uv.x - vv.x - acc[j][0]);
        vn.y = vv.y + ETA_C * (uv.y - vv.y - acc[j][1]);
        vn.z = vv.z + ETA_C * (uv.z - vv.z - acc[j][2]);
        vn.w = vv.w + ETA_C * (uv.w - vv.w - acc[j][3]);
        *(float4*)(vrow + c) = vn;
        float s, o0, o1, o2, o3;
        s = fabsf(vn.x) - lam; o0 = (s > 0.f) ? copysignf(s, vn.x) : 0.f;
        s = fabsf(vn.y) - lam; o1 = (s > 0.f) ? copysignf(s, vn.y) : 0.f;
        s = fabsf(vn.z) - lam; o2 = (s > 0.f) ? copysignf(s, vn.z) : 0.f;
        s = fabsf(vn.w) - lam; o3 = (s > 0.f) ? copysignf(s, vn.w) : 0.f;
        uint2 pk = make_uint2(h2pack(o0, o1), h2pack(o2, o3));
        *(uint2*)(orow + c) = pk;
    }
}

// ---------------- small kernels ----------------
__global__ void round_copy_h(const float* __restrict__ in, __half* __restrict__ out)
{
    const long i = ((long)blockIdx.x * blockDim.x + threadIdx.x) * 4;
    float4 v = *(const float4*)(in + i);
    uint2 pk = make_uint2(h2pack(v.x, v.y), h2pack(v.z, v.w));
    *(uint2*)(out + i) = pk;
}

__global__ void symzero2(const float* __restrict__ Gq, const float* __restrict__ Gk,
                         __half* __restrict__ Gs)
{
    const long idx = (long)blockIdx.x * blockDim.x + threadIdx.x;
    const long e = idx & (DD - 1);
    const float* G = (idx < DD) ? Gq : Gk;
    const int i = (int)(e / D_SZ), j = (int)(e % D_SZ);
    Gs[idx] = (i == j) ? __float2half_rn(0.f)
                       : __float2half_rn(0.5f * (G[e] + G[(long)j * D_SZ + i]));
}

// V [B][T][D] fp32 -> Vt [B][D][T] fp16
__global__ void transpose_bt(const float* __restrict__ in, __half* __restrict__ out)
{
    __shared__ float t[32][33];
    const int b = blockIdx.z;
    const int t0 = blockIdx.x * 32, d0 = blockIdx.y * 32;
    in  += (long)b * TD;
    out += (long)b * TD;
    const int x = threadIdx.x, y = threadIdx.y;
#pragma unroll
    for (int i = 0; i < 32; i += 8)
        t[y + i][x] = in[(long)(t0 + y + i) * D_SZ + d0 + x];
    __syncthreads();
#pragma unroll
    for (int i = 0; i < 32; i += 8)
        out[(long)(d0 + y + i) * T_SZ + t0 + x] = __float2half_rn(t[x][y + i]);
}

// causal softmax: reads fp32 scores S, writes fp16 probs Ph (tail zeroed)
__global__ void softmax_causal(const float* __restrict__ S, __half* __restrict__ Ph)
{
    const int i = blockIdx.x;
    const int b = blockIdx.y;
    const float* row = S + ((long)b * T_SZ + i) * T_SZ;
    __half* prow = Ph + ((long)b * T_SZ + i) * T_SZ;
    const int tid = threadIdx.x;
    const int n = i + 1;
    __shared__ float red[256];

    float mx = -INFINITY;
    for (int j = tid; j < n; j += 256) mx = fmaxf(mx, row[j]);
    red[tid] = mx;
    __syncthreads();
    for (int s = 128; s > 0; s >>= 1) {
        if (tid < s) red[tid] = fmaxf(red[tid], red[tid + s]);
        __syncthreads();
    }
    mx = red[0];
    __syncthreads();

    float sum = 0.f;
    for (int j = tid; j < n; j += 256) {
        float e = expf(row[j] - mx);
        prow[j] = __float2half_rn(e);
        sum += e;
    }
    red[tid] = sum;
    __syncthreads();
    for (int s = 128; s > 0; s >>= 1) {
        if (tid < s) red[tid] += red[tid + s];
        __syncthreads();
    }
    const float inv = 1.f / red[0];
    for (int j = tid; j < n; j += 256)
        prow[j] = __float2half_rn(__half2float(prow[j]) * inv);
    for (int j = n + tid; j < T_SZ; j += 256) prow[j] = __float2half_rn(0.f);
}

// ---------------- launch ----------------
extern "C" void kernel_launch(void* const* d_in, const int* in_sizes, int n_in,
                              void* d_out, int out_size)
{
    const float* x        = (const float*)d_in[0];
    const float* W_qkv    = (const float*)d_in[1];
    const float* W_out    = (const float*)d_in[2];
    const float* Gq_raw   = (const float*)d_in[3];
    const float* loglam_q = (const float*)d_in[4];
    const float* Gk_raw   = (const float*)d_in[5];
    const float* loglam_k = (const float*)d_in[6];
    float* out = (float*)d_out;
    (void)in_sizes; (void)n_in; (void)out_size;

    float *u3, *vs, *S;
    __half *vt, *abb, *G2h, *Ph, *o, *xr, *wqr, *wor;
    cudaGetSymbolAddress((void**)&u3,  g_u3);
    cudaGetSymbolAddress((void**)&vt,  g_vt);
    cudaGetSymbolAddress((void**)&vs,  g_vs);
    cudaGetSymbolAddress((void**)&abb, g_ab);
    cudaGetSymbolAddress((void**)&G2h, g_G2);
    cudaGetSymbolAddress((void**)&S,   g_S);
    cudaGetSymbolAddress((void**)&Ph,  g_Ph);
    cudaGetSymbolAddress((void**)&o,   g_o);
    cudaGetSymbolAddress((void**)&xr,  g_xr);
    cudaGetSymbolAddress((void**)&wqr, g_wqkvr);
    cudaGetSymbolAddress((void**)&wor, g_woutr);

    cudaFuncSetAttribute(mm_f16<MODE_QKV>,   cudaFuncAttributeMaxDynamicSharedMemorySize, GSMEM_BYTES);
    cudaFuncSetAttribute(mm_f16<MODE_LCA>,   cudaFuncAttributeMaxDynamicSharedMemorySize, GSMEM_BYTES);
    cudaFuncSetAttribute(mm_f16<MODE_SCORE>, cudaFuncAttributeMaxDynamicSharedMemorySize, GSMEM_BYTES);
    cudaFuncSetAttribute(mm_f16<MODE_PV>,    cudaFuncAttributeMaxDynamicSharedMemorySize, GSMEM_BYTES);
    cudaFuncSetAttribute(mm_f16<MODE_PLAIN>, cudaFuncAttributeMaxDynamicSharedMemorySize, GSMEM_BYTES);

    __half* ab[2] = { abb, abb + 2 * MD };
    float* vvv = u3 + 2 * MD;

    const dim3 thr(256);

    // 0) pre-round raw GEMM inputs to fp16
    round_copy_h<<<(unsigned)(MD / 1024), thr>>>(x, xr);
    round_copy_h<<<(unsigned)(3 * DD / 1024), thr>>>(W_qkv, wqr);
    round_copy_h<<<(unsigned)(DD / 1024), thr>>>(W_out, wor);

    // 1) symmetrize + zero-diag both G's (fp16)
    symzero2<<<(unsigned)(2 * DD / 256), thr>>>(Gq_raw, Gk_raw, G2h);

    // 2) QKV projections + fused LCA iteration 1 (z<2 writes vs, a0)
    {
        dim3 g(D_SZ / 128, M_SZ / 128, 3);
        mm_f16<MODE_QKV><<<g, thr, GSMEM_BYTES>>>(xr, wqr, u3, D_SZ, D_SZ, D_SZ, D_SZ, 1.f,
                                                  0, DD, MD, nullptr, vs, ab[0],
                                                  loglam_q, loglam_k);
    }

    // 3) transpose V (fp32 -> fp16)
    {
        dim3 g(T_SZ / 32, D_SZ / 32, B_SZ);
        transpose_bt<<<g, dim3(32, 8)>>>(vvv, vt);
    }

    // 4) LCA iterations 2..3: SPARSE (a nearly empty)
    int cur = 0;
    {
        const unsigned g = (unsigned)(2 * M_SZ / 8);   // warp per row, 8 warps/CTA
        for (int it = 0; it < LCA_SPARSE_ITERS; it++) {
            lca_sparse<<<g, thr>>>(ab[cur], G2h, u3, vs, ab[cur ^ 1], loglam_q, loglam_k);
            cur ^= 1;
        }
    }

    // 5) LCA iterations 4..10: dense fp16 tensor GEMM + prox, q+k merged over z
    {
        dim3 g(D_SZ / 128, M_SZ / 128, 2);
        for (int it = 0; it < LCA_DENSE_ITERS; it++) {
            mm_f16<MODE_LCA><<<g, thr, GSMEM_BYTES>>>(ab[cur], G2h, ab[cur ^ 1],
                                                      D_SZ, D_SZ, D_SZ, D_SZ, 1.f,
                                                      MD, DD, MD, u3, vs, nullptr,
                                                      loglam_q, loglam_k);
            cur ^= 1;
        }
    }
    __half* qf = ab[cur];
    __half* kf = ab[cur] + MD;

    // 6) scores S = q k^T / 32, triangular grid (136 live tiles x batch), fp32 out
    {
        dim3 g(136, 1, B_SZ);
        mm_f16<MODE_SCORE><<<g, thr, GSMEM_BYTES>>>(qf, kf, S, D_SZ, D_SZ, D_SZ, T_SZ, 0.03125f,
                                                    TD, TD, TT, nullptr, nullptr, nullptr,
                                                    nullptr, nullptr);
    }

    // 7) causal softmax: fp32 scores -> fp16 probs
    {
        dim3 g(T_SZ, B_SZ);
        softmax_causal<<<g, thr>>>(S, Ph);
    }

    // 8) o = P @ V (NT against Vt, causal K-limit), fp16 out
    {
        dim3 g(D_SZ / 128, T_SZ / 128, B_SZ);
        mm_f16<MODE_PV><<<g, thr, GSMEM_BYTES>>>(Ph, vt, o, T_SZ, T_SZ, T_SZ, D_SZ, 1.f,
                                                 TT, TD, TD, nullptr, nullptr, nullptr,
                                                 nullptr, nullptr);
    }

    // 9) out = o @ W_out^T (fp32 output)
    {
        dim3 g(D_SZ / 128, M_SZ / 128, 1);
        mm_f16<MODE_PLAIN><<<g, thr, GSMEM_BYTES>>>(o, wor, out, D_SZ, D_SZ, D_SZ, D_SZ, 1.f,
                                                    0, 0, 0, nullptr, nullptr, nullptr,
                                                    nullptr, nullptr);
    }
}

// round 12
// speedup vs baseline: 2.3609x; 1.0093x over previous
#include <cuda_runtime.h>
#include <cuda_fp16.h>
#include <cstdint>
#include <math.h>

// ---------------- problem constants ----------------
#define B_SZ 4
#define T_SZ 2048
#define D_SZ 1024
#define M_SZ (B_SZ * T_SZ)
#define MD   ((long)M_SZ * D_SZ)
#define DD   ((long)D_SZ * D_SZ)
#define TT   ((long)T_SZ * T_SZ)
#define TD   ((long)T_SZ * D_SZ)
#define ETA_C 0.1f
#define LCA_SPARSE_ITERS 2
#define LCA_DENSE_ITERS  7

// ---------------- scratch (device globals; no allocation) ----------------
__device__ __half g_u3[3 * M_SZ * D_SZ];     // u_q, u_k, v (fp16)
__device__ __half g_vt[M_SZ * D_SZ];         // V^T per batch [B][D][T] (fp16)
__device__ float  g_vs[2 * M_SZ * D_SZ];     // LCA v-state (fp32)
__device__ __half g_ab[2][2 * M_SZ * D_SZ];  // LCA codes ping-pong x (q,k) (fp16)
__device__ __half g_G2[2 * D_SZ * D_SZ];     // sym zero-diag Gq,Gk (fp16)
__device__ float  g_S[(size_t)B_SZ * T_SZ * T_SZ];   // scores (fp32)
__device__ __half g_Ph[(size_t)B_SZ * T_SZ * T_SZ];  // probs (fp16)
__device__ __half g_o[M_SZ * D_SZ];          // attention out (fp16)
__device__ __half g_xr[M_SZ * D_SZ];         // x (fp16)
__device__ __half g_wqkvr[3 * D_SZ * D_SZ];  // W_qkv (fp16)
__device__ __half g_woutr[D_SZ * D_SZ];      // W_out (fp16)

// ---------------- helpers ----------------
__device__ __forceinline__ uint32_t smem_u32(const void* p) {
    uint32_t a;
    asm("{ .reg .u64 t; cvta.to.shared.u64 t, %1; cvt.u32.u64 %0, t; }" : "=r"(a) : "l"(p));
    return a;
}
__device__ __forceinline__ void cp_async16(uint32_t dst, const void* src) {
    asm volatile("cp.async.cg.shared.global [%0], [%1], 16;" :: "r"(dst), "l"(src));
}
#define CP_COMMIT() asm volatile("cp.async.commit_group;" ::: "memory")
#define CP_WAIT1()  asm volatile("cp.async.wait_group 1;" ::: "memory")
#define CP_WAIT0()  asm volatile("cp.async.wait_group 0;" ::: "memory")

#define LDSM_X4(r, addr) \
    asm volatile("ldmatrix.sync.aligned.m8n8.x4.shared.b16 {%0,%1,%2,%3}, [%4];" \
                 : "=r"((r)[0]), "=r"((r)[1]), "=r"((r)[2]), "=r"((r)[3]) : "r"(addr))

__device__ __forceinline__ void mma_f16(float* c, const uint32_t* a, const uint32_t* b) {
    asm volatile(
        "mma.sync.aligned.m16n8k16.row.col.f32.f16.f16.f32 "
        "{%0,%1,%2,%3}, {%4,%5,%6,%7}, {%8,%9}, {%0,%1,%2,%3};"
        : "+f"(c[0]), "+f"(c[1]), "+f"(c[2]), "+f"(c[3])
        : "r"(a[0]), "r"(a[1]), "r"(a[2]), "r"(a[3]), "r"(b[0]), "r"(b[1]));
}
__device__ __forceinline__ uint32_t h2pack(float a, float b) {
    __half2 h = __floats2half2_rn(a, b);
    return *reinterpret_cast<uint32_t*>(&h);
}
__device__ __forceinline__ float2 h2unpack(uint32_t u) {
    return __half22float2(*reinterpret_cast<__half2*>(&u));
}

// ---------------- GEMM (NT, fp16 in / fp32 acc): C = alpha * A B^T --------------
// R5/R11-proven shape: 128x128 CTA tile, 8 warps of 64x32, 2 CTAs/SM, BK=64,
// 2-stage cp.async (issue-then-WAIT1, two barriers/chunk). NEW: natural smem
// layout (144B rows) + ldmatrix.x4 fragment loads (canonical mma fragments,
// conflict-free: row stride 36 uint32 = 4 banks -> 8-row phase covers all 32).
#define MODE_QKV   0   // C=u fp16; for z<2 also vs=eta*u (fp32), a0=soft (fp16)
#define MODE_LCA   1   // fused LCA prox; writes fp16 a
#define MODE_SCORE 2   // triangular-grid decode; writes fp32 S
#define MODE_PV    3   // causal K-limit; writes fp16 o
#define MODE_PLAIN 4   // writes fp32 out

#define BK     64
#define ROWB   144                     // bytes per smem row (128 data + 16 pad)
#define TILE_B (128 * ROWB)            // 18432 B per operand tile
#define GSMEM_BYTES (4 * TILE_B)       // 2 A + 2 B stages = 73728 B

template <int MODE>
__global__ void __launch_bounds__(256, 2)
mm_f16(const __half* __restrict__ A, const __half* __restrict__ Bm, void* __restrict__ Cv,
       int K, int ldA, int ldB, int ldC, float alpha,
       long sA, long sB, long sC,
       const __half* __restrict__ U, float* __restrict__ Vst, __half* __restrict__ Aux,
       const float* __restrict__ llq, const float* __restrict__ llk)
{
    int r0, c0;
    if (MODE == MODE_SCORE) {
        const int t = blockIdx.x;                 // t = by*(by+1)/2 + bx, bx<=by
        int by = (int)((sqrtf(8.f * t + 1.f) - 1.f) * 0.5f);
        while ((by + 1) * (by + 2) / 2 <= t) by++;
        while (by * (by + 1) / 2 > t) by--;
        const int bx = t - by * (by + 1) / 2;
        r0 = by * 128; c0 = bx * 128;
    } else {
        r0 = blockIdx.y * 128;
        c0 = blockIdx.x * 128;
    }

    const long bz = blockIdx.z;
    A  += bz * sA;
    Bm += bz * sB;

    extern __shared__ char smem[];
    const uint32_t sbase = smem_u32(smem);

    const int tid  = threadIdx.x;
    const int lane = tid & 31;
    const int wid  = tid >> 5;
    const int wm   = (wid >> 2) * 64;
    const int wn   = (wid & 3) * 32;
    const int lr   = lane >> 2;         // 0..7
    const int lc   = lane & 3;          // 0..3

    // ldmatrix per-lane address offsets (within a tile)
    const uint32_t a_lm = (uint32_t)(wm + (lane & 15)) * ROWB + (lane & 16);
    const uint32_t b_lm = (uint32_t)(wn + (lane & 7) + ((lane >> 1) & 8)) * ROWB
                        + ((lane << 1) & 16);

    const int kmax = (MODE == MODE_PV) ? min(K, r0 + 128) : K;
    const int nch  = kmax / BK;

    float acc[4][4][4];
#pragma unroll
    for (int i = 0; i < 4; i++)
#pragma unroll
        for (int j = 0; j < 4; j++)
#pragma unroll
            for (int e = 0; e < 4; e++) acc[i][j][e] = 0.f;

    auto issue = [&](int c) {
        const int buf = c & 1;
        const __half* Ac = A  + (long)r0 * ldA + c * BK;
        const __half* Bc = Bm + (long)c0 * ldB + c * BK;
        const uint32_t ab = sbase + buf * TILE_B;
        const uint32_t bb = sbase + 2 * TILE_B + buf * TILE_B;
#pragma unroll
        for (int i = 0; i < 4; i++) {
            const int idx = tid + i * 256;       // 1024 16B granules per tile
            const int row = idx >> 3, c8 = idx & 7;
            cp_async16(ab + (uint32_t)(row * ROWB + c8 * 16), Ac + (long)row * ldA + c8 * 8);
            cp_async16(bb + (uint32_t)(row * ROWB + c8 * 16), Bc + (long)row * ldB + c8 * 8);
        }
        CP_COMMIT();
    };

    issue(0);
    for (int c = 0; c < nch; c++) {
        if (c + 1 < nch) { issue(c + 1); CP_WAIT1(); }
        else             { CP_WAIT0(); }
        __syncthreads();

        const uint32_t Aad = sbase + (c & 1) * TILE_B + a_lm;
        const uint32_t Bad = sbase + 2 * TILE_B + (c & 1) * TILE_B + b_lm;
#pragma unroll
        for (int g = 0; g < 4; g++) {            // four 16-k groups per chunk
            const uint32_t goff = g * 32;        // bytes
            uint32_t af[4][4], bf[2][4];
#pragma unroll
            for (int mt = 0; mt < 4; mt++)
                LDSM_X4(af[mt], Aad + mt * (16 * ROWB) + goff);
#pragma unroll
            for (int p = 0; p < 2; p++)
                LDSM_X4(bf[p], Bad + p * (16 * ROWB) + goff);
#pragma unroll
            for (int mt = 0; mt < 4; mt++)
#pragma unroll
                for (int nt = 0; nt < 4; nt++)
                    mma_f16(acc[mt][nt], af[mt], &bf[nt >> 1][(nt & 1) * 2]);
        }
        __syncthreads();
    }

    // ---------------- epilogue ----------------
    float lam = 0.f;
    if (MODE == MODE_LCA || (MODE == MODE_QKV && bz < 2))
        lam = expf(bz == 0 ? *llq : *llk);
#pragma unroll
    for (int mt = 0; mt < 4; mt++) {
#pragma unroll
        for (int h = 0; h < 2; h++) {
            const int row = r0 + wm + mt * 16 + lr + h * 8;
#pragma unroll
            for (int nt = 0; nt < 4; nt++) {
                const int col = c0 + wn + nt * 8 + lc * 2;
                const long idx = (long)row * ldC + col;
                float x0 = acc[mt][nt][h * 2 + 0];
                float x1 = acc[mt][nt][h * 2 + 1];
                if (MODE == MODE_LCA) {
                    __half* Ch = (__half*)Cv + bz * sC;
                    float2 u2 = h2unpack(*(const uint32_t*)(U + bz * sC + idx));
                    float2 v2 = *(const float2*)(Vst + bz * sC + idx);
                    float2 vn;
                    vn.x = v2.x + ETA_C * (u2.x - v2.x - x0);
                    vn.y = v2.y + ETA_C * (u2.y - v2.y - x1);
                    *(float2*)(Vst + bz * sC + idx) = vn;
                    float s, o0, o1;
                    s = fabsf(vn.x) - lam; o0 = (s > 0.f) ? copysignf(s, vn.x) : 0.f;
                    s = fabsf(vn.y) - lam; o1 = (s > 0.f) ? copysignf(s, vn.y) : 0.f;
                    *(uint32_t*)(Ch + idx) = h2pack(o0, o1);
                } else if (MODE == MODE_QKV) {
                    __half* Ch = (__half*)Cv + bz * sC;
                    *(uint32_t*)(Ch + idx) = h2pack(x0, x1);         // u (fp16)
                    if (bz < 2) {                                    // fused LCA iter 1
                        float2 vn = make_float2(ETA_C * x0, ETA_C * x1);
                        *(float2*)(Vst + bz * sC + idx) = vn;
                        float s, o0, o1;
                        s = fabsf(vn.x) - lam; o0 = (s > 0.f) ? copysignf(s, vn.x) : 0.f;
                        s = fabsf(vn.y) - lam; o1 = (s > 0.f) ? copysignf(s, vn.y) : 0.f;
                        *(uint32_t*)(Aux + bz * sC + idx) = h2pack(o0, o1);
                    }
                } else if (MODE == MODE_PV) {
                    __half* Ch = (__half*)Cv + bz * sC;
                    *(uint32_t*)(Ch + idx) = h2pack(x0, x1);
                } else {  // SCORE / PLAIN -> fp32
                    float* Cf = (float*)Cv + bz * sC;
                    *(float2*)(Cf + idx) = make_float2(alpha * x0, alpha * x1);
                }
            }
        }
    }
}

// ---------------- sparse LCA iteration: warp per row (fp16 a/G/u) -------------
__global__ void __launch_bounds__(256, 4)
lca_sparse(const __half* __restrict__ a_in, const __half* __restrict__ G2,
           const __half* __restrict__ U, float* __restrict__ Vst,
           __half* __restrict__ a_out,
           const float* __restrict__ llq, const float* __restrict__ llk)
{
    const long row  = ((long)blockIdx.x * blockDim.x + threadIdx.x) >> 5;
    const int  lane = threadIdx.x & 31;
    const int  half = (row >= M_SZ);
    const __half* G = G2 + (long)half * DD;
    const float lam = expf(half ? *llk : *llq);

    const __half* arow = a_in + row * D_SZ;

    float acc[8][4];
#pragma unroll
    for (int j = 0; j < 8; j++)
#pragma unroll
        for (int i = 0; i < 4; i++) acc[j][i] = 0.f;

#pragma unroll
    for (int j = 0; j < 8; j++) {
        const __half2* ap = (const __half2*)(arow + lane * 4 + 128 * j);
        const float2 f0 = __half22float2(ap[0]);
        const float2 f1 = __half22float2(ap[1]);
        const float vals[4] = { f0.x, f0.y, f1.x, f1.y };
#pragma unroll
        for (int i = 0; i < 4; i++) {
            unsigned m = __ballot_sync(0xFFFFFFFFu, vals[i] != 0.f);
            while (m) {
                const int s = __ffs(m) - 1;
                m &= m - 1;
                const float aval = __shfl_sync(0xFFFFFFFFu, vals[i], s);
                const int k = s * 4 + 128 * j + i;
                const __half* Gr = G + (long)k * D_SZ + lane * 4;
#pragma unroll
                for (int jj = 0; jj < 8; jj++) {
                    const __half2* gp = (const __half2*)(Gr + 128 * jj);
                    const float2 g0 = __half22float2(gp[0]);
                    const float2 g1 = __half22float2(gp[1]);
                    acc[jj][0] += aval * g0.x;
                    acc[jj][1] += aval * g0.y;
                    acc[jj][2] += aval * g1.x;
                    acc[jj][3] += aval * g1.y;
                }
            }
        }
    }

    const __half* urow = U + row * D_SZ;
    float* vrow = Vst + row * D_SZ;
    __half* orow = a_out + row * D_SZ;
#pragma unroll
    for (int j = 0; j < 8; j++) {
        const int c = lane * 4 + 128 * j;
        const __half2* up = (const __half2*)(urow + c);
        const float2 u0 = __half22float2(up[0]);
        const float2 u1 = __half22float2(up[1]);
        const float4 vv = *(const float4*)(vrow + c);
        float4 vn;
        vn.x = vv.x + ETA_C * (u0.x - vv.x - acc[j][0]);
        vn.y = vv.y + ETA_C * (u0.y - vv.y - acc[j][1]);
        vn.z = vv.z + ETA_C * (u1.x - vv.z - acc[j][2]);
        vn.w = vv.w + ETA_C * (u1.y - vv.w - acc[j][3]);
        *(float4*)(vrow + c) = vn;
        float s, o0, o1, o2, o3;
        s = fabsf(vn.x) - lam; o0 = (s > 0.f) ? copysignf(s, vn.x) : 0.f;
        s = fabsf(vn.y) - lam; o1 = (s > 0.f) ? copysignf(s, vn.y) : 0.f;
        s = fabsf(vn.z) - lam; o2 = (s > 0.f) ? copysignf(s, vn.z) : 0.f;
        s = fabsf(vn.w) - lam; o3 = (s > 0.f) ? copysignf(s, vn.w) : 0.f;
        uint2 pk = make_uint2(h2pack(o0, o1), h2pack(o2, o3));
        *(uint2*)(orow + c) = pk;
    }
}

// ---------------- small kernels ----------------
__global__ void round_copy_h(const float* __restrict__ in, __half* __restrict__ out)
{
    const long i = ((long)blockIdx.x * blockDim.x + threadIdx.x) * 4;
    float4 v = *(const float4*)(in + i);
    uint2 pk = make_uint2(h2pack(v.x, v.y), h2pack(v.z, v.w));
    *(uint2*)(out + i) = pk;
}

__global__ void symzero2(const float* __restrict__ Gq, const float* __restrict__ Gk,
                         __half* __restrict__ Gs)
{
    const long idx = (long)blockIdx.x * blockDim.x + threadIdx.x;
    const long e = idx & (DD - 1);
    const float* G = (idx < DD) ? Gq : Gk;
    const int i = (int)(e / D_SZ), j = (int)(e % D_SZ);
    Gs[idx] = (i == j) ? __float2half_rn(0.f)
                       : __float2half_rn(0.5f * (G[e] + G[(long)j * D_SZ + i]));
}

// V [B][T][D] fp16 -> Vt [B][D][T] fp16 (exact move through fp32 staging)
__global__ void transpose_bt(const __half* __restrict__ in, __half* __restrict__ out)
{
    __shared__ float t[32][33];
    const int b = blockIdx.z;
    const int t0 = blockIdx.x * 32, d0 = blockIdx.y * 32;
    in  += (long)b * TD;
    out += (long)b * TD;
    const int x = threadIdx.x, y = threadIdx.y;
#pragma unroll
    for (int i = 0; i < 32; i += 8)
        t[y + i][x] = __half2float(in[(long)(t0 + y + i) * D_SZ + d0 + x]);
    __syncthreads();
#pragma unroll
    for (int i = 0; i < 32; i += 8)
        out[(long)(d0 + y + i) * T_SZ + t0 + x] = __float2half_rn(t[x][y + i]);
}

// causal softmax: reads fp32 scores S, writes fp16 probs Ph (tail zeroed)
__global__ void softmax_causal(const float* __restrict__ S, __half* __restrict__ Ph)
{
    const int i = blockIdx.x;
    const int b = blockIdx.y;
    const float* row = S + ((long)b * T_SZ + i) * T_SZ;
    __half* prow = Ph + ((long)b * T_SZ + i) * T_SZ;
    const int tid = threadIdx.x;
    const int n = i + 1;
    __shared__ float red[256];

    float mx = -INFINITY;
    for (int j = tid; j < n; j += 256) mx = fmaxf(mx, row[j]);
    red[tid] = mx;
    __syncthreads();
    for (int s = 128; s > 0; s >>= 1) {
        if (tid < s) red[tid] = fmaxf(red[tid], red[tid + s]);
        __syncthreads();
    }
    mx = red[0];
    __syncthreads();

    float sum = 0.f;
    for (int j = tid; j < n; j += 256) {
        float e = expf(row[j] - mx);
        prow[j] = __float2half_rn(e);
        sum += e;
    }
    red[tid] = sum;
    __syncthreads();
    for (int s = 128; s > 0; s >>= 1) {
        if (tid < s) red[tid] += red[tid + s];
        __syncthreads();
    }
    const float inv = 1.f / red[0];
    for (int j = tid; j < n; j += 256)
        prow[j] = __float2half_rn(__half2float(prow[j]) * inv);
    for (int j = n + tid; j < T_SZ; j += 256) prow[j] = __float2half_rn(0.f);
}

// ---------------- launch ----------------
extern "C" void kernel_launch(void* const* d_in, const int* in_sizes, int n_in,
                              void* d_out, int out_size)
{
    const float* x        = (const float*)d_in[0];
    const float* W_qkv    = (const float*)d_in[1];
    const float* W_out    = (const float*)d_in[2];
    const float* Gq_raw   = (const float*)d_in[3];
    const float* loglam_q = (const float*)d_in[4];
    const float* Gk_raw   = (const float*)d_in[5];
    const float* loglam_k = (const float*)d_in[6];
    float* out = (float*)d_out;
    (void)in_sizes; (void)n_in; (void)out_size;

    float *vs, *S;
    __half *u3, *vt, *abb, *G2h, *Ph, *o, *xr, *wqr, *wor;
    cudaGetSymbolAddress((void**)&u3,  g_u3);
    cudaGetSymbolAddress((void**)&vt,  g_vt);
    cudaGetSymbolAddress((void**)&vs,  g_vs);
    cudaGetSymbolAddress((void**)&abb, g_ab);
    cudaGetSymbolAddress((void**)&G2h, g_G2);
    cudaGetSymbolAddress((void**)&S,   g_S);
    cudaGetSymbolAddress((void**)&Ph,  g_Ph);
    cudaGetSymbolAddress((void**)&o,   g_o);
    cudaGetSymbolAddress((void**)&xr,  g_xr);
    cudaGetSymbolAddress((void**)&wqr, g_wqkvr);
    cudaGetSymbolAddress((void**)&wor, g_woutr);

    cudaFuncSetAttribute(mm_f16<MODE_QKV>,   cudaFuncAttributeMaxDynamicSharedMemorySize, GSMEM_BYTES);
    cudaFuncSetAttribute(mm_f16<MODE_LCA>,   cudaFuncAttributeMaxDynamicSharedMemorySize, GSMEM_BYTES);
    cudaFuncSetAttribute(mm_f16<MODE_SCORE>, cudaFuncAttributeMaxDynamicSharedMemorySize, GSMEM_BYTES);
    cudaFuncSetAttribute(mm_f16<MODE_PV>,    cudaFuncAttributeMaxDynamicSharedMemorySize, GSMEM_BYTES);
    cudaFuncSetAttribute(mm_f16<MODE_PLAIN>, cudaFuncAttributeMaxDynamicSharedMemorySize, GSMEM_BYTES);

    __half* ab[2] = { abb, abb + 2 * MD };
    __half* vvv = u3 + 2 * MD;

    const dim3 thr(256);

    // 0) pre-round raw GEMM inputs to fp16
    round_copy_h<<<(unsigned)(MD / 1024), thr>>>(x, xr);
    round_copy_h<<<(unsigned)(3 * DD / 1024), thr>>>(W_qkv, wqr);
    round_copy_h<<<(unsigned)(DD / 1024), thr>>>(W_out, wor);

    // 1) symmetrize + zero-diag both G's (fp16)
    symzero2<<<(unsigned)(2 * DD / 256), thr>>>(Gq_raw, Gk_raw, G2h);

    // 2) QKV projections + fused LCA iteration 1 (z<2 writes vs, a0)
    {
        dim3 g(D_SZ / 128, M_SZ / 128, 3);
        mm_f16<MODE_QKV><<<g, thr, GSMEM_BYTES>>>(xr, wqr, u3, D_SZ, D_SZ, D_SZ, D_SZ, 1.f,
                                                  0, DD, MD, nullptr, vs, ab[0],
                                                  loglam_q, loglam_k);
    }

    // 3) transpose V (fp16)
    {
        dim3 g(T_SZ / 32, D_SZ / 32, B_SZ);
        transpose_bt<<<g, dim3(32, 8)>>>(vvv, vt);
    }

    // 4) LCA iterations 2..3: SPARSE (a nearly empty)
    int cur = 0;
    {
        const unsigned g = (unsigned)(2 * M_SZ / 8);   // warp per row, 8 warps/CTA
        for (int it = 0; it < LCA_SPARSE_ITERS; it++) {
            lca_sparse<<<g, thr>>>(ab[cur], G2h, u3, vs, ab[cur ^ 1], loglam_q, loglam_k);
            cur ^= 1;
        }
    }

    // 5) LCA iterations 4..10: dense fp16 tensor GEMM + prox, q+k merged over z
    {
        dim3 g(D_SZ / 128, M_SZ / 128, 2);
        for (int it = 0; it < LCA_DENSE_ITERS; it++) {
            mm_f16<MODE_LCA><<<g, thr, GSMEM_BYTES>>>(ab[cur], G2h, ab[cur ^ 1],
                                                      D_SZ, D_SZ, D_SZ, D_SZ, 1.f,
                                                      MD, DD, MD, u3, vs, nullptr,
                                                      loglam_q, loglam_k);
            cur ^= 1;
        }
    }
    __half* qf = ab[cur];
    __half* kf = ab[cur] + MD;

    // 6) scores S = q k^T / 32, triangular grid (136 live tiles x batch), fp32 out
    {
        dim3 g(136, 1, B_SZ);
        mm_f16<MODE_SCORE><<<g, thr, GSMEM_BYTES>>>(qf, kf, S, D_SZ, D_SZ, D_SZ, T_SZ, 0.03125f,
                                                    TD, TD, TT, nullptr, nullptr, nullptr,
                                                    nullptr, nullptr);
    }

    // 7) causal softmax: fp32 scores -> fp16 probs
    {
        dim3 g(T_SZ, B_SZ);
        softmax_causal<<<g, thr>>>(S, Ph);
    }

    // 8) o = P @ V (NT against Vt, causal K-limit), fp16 out
    {
        dim3 g(D_SZ / 128, T_SZ / 128, B_SZ);
        mm_f16<MODE_PV><<<g, thr, GSMEM_BYTES>>>(Ph, vt, o, T_SZ, T_SZ, T_SZ, D_SZ, 1.f,
                                                 TT, TD, TD, nullptr, nullptr, nullptr,
                                                 nullptr, nullptr);
    }

    // 9) out = o @ W_out^T (fp32 output)
    {
        dim3 g(D_SZ / 128, M_SZ / 128, 1);
        mm_f16<MODE_PLAIN><<<g, thr, GSMEM_BYTES>>>(o, wor, out, D_SZ, D_SZ, D_SZ, D_SZ, 1.f,
                                                    0, 0, 0, nullptr, nullptr, nullptr,
                                                    nullptr, nullptr);
    }
}